// round 11
// baseline (speedup 1.0000x reference)
#include <cuda_runtime.h>
#include <math.h>

#define NG 192
#define NTOT (NG * NG * NG)
#define BX 32
#define BY 4
#define BZ 4
#define TX (BX + 4)      // 36
#define TY (BY + 4)      // 8
#define TZ (BZ + 2)      // 6 : halo only on +z (forward offsets)
#define TILE (TX * TY * TZ)   // 1728

#define KN   500000.0f
#define MU   0.5f
#define EPSF 1e-4f
#define FULLMASK 0xffffffffu
#define BMASK 0x00FEFEFEu
#define LCAP (1 << 20)   // hit-list capacity (voxel indices); ~500 expected

// hit list + counter; reset kernel zeroes the counter every run, so graph
// replays are deterministic. No dynamic allocation.
__device__ int g_count;
__device__ int g_list[LCAP];

__device__ __forceinline__ int wrapN(int v) {
    if (v < 0) v += NG;
    if (v >= NG) v -= NG;
    return v;
}

// exact per-voxel evaluation + store (pass B; idempotent per voxel)
__device__ __noinline__ void exact_voxel_store(
    int ga, int gb, int gc, float two_d, float eta,
    const float* __restrict__ xg, const float* __restrict__ yg,
    const float* __restrict__ zg, const float* __restrict__ vxg,
    const float* __restrict__ vyg, const float* __restrict__ vzg,
    float* __restrict__ out)
{
    const float two_d2 = two_d * two_d;
    const int gidx = (ga * NG + gb) * NG + gc;
    const float px = xg[gidx], py = yg[gidx], pz = zg[gidx];
    const float pvx = vxg[gidx], pvy = vyg[gidx], pvz = vzg[gidx];
    float fxc = 0.f, fyc = 0.f, fzc = 0.f;
    float fxd = 0.f, fyd = 0.f, fzd = 0.f;
    float frx = 0.f, fry = 0.f, frz = 0.f;
    #pragma unroll 1
    for (int oz = -2; oz <= 2; oz++) {
        const int na = wrapN(ga + oz);
        #pragma unroll 1
        for (int oy = -2; oy <= 2; oy++) {
            const int nb = wrapN(gb + oy);
            const int rowb = (na * NG + nb) * NG;
            #pragma unroll 1
            for (int ox = -2; ox <= 2; ox++) {
                const int nc = wrapN(gc + ox);
                const int nidx = rowb + nc;
                const float dx = px - xg[nidx];
                const float dy = py - yg[nidx];
                const float dz = pz - zg[nidx];
                const float d2 = fmaf(dz, dz, fmaf(dy, dy, dx * dx));
                // d2 == 0 (incl. self) contributes exactly 0 -> skip
                const bool hit = (d2 < two_d2) && (d2 > 0.0f);
                if (hit) {
                    const float dist = sqrtf(d2);
                    const float safe = fmaxf(EPSF, dist);
                    const float inv  = 1.0f / safe;
                    const float coef = KN * (dist - two_d) * inv;
                    fxc += coef * dx;
                    fyc += coef * dy;
                    fzc += coef * dz;
                    const float dvx = pvx - vxg[nidx];
                    const float dvy = pvy - vyg[nidx];
                    const float dvz = pvz - vzg[nidx];
                    const float vn  = (dvx * dx + dvy * dy + dvz * dz) * inv;
                    const float c2  = eta * vn * inv;
                    fxd += c2 * dx;
                    fyd += c2 * dy;
                    fzd += c2 * dz;
                }
            }
        }
    }
    // friction: only the LAST scan shift s=(2,2,2) survives, i.e. neighbor
    // offset (-2,-2,-2), evaluated against the fully accumulated sums.
    // NOTE: includes d2 == 0 overlaps (no d2 > 0 exclusion here).
    {
        const int na = wrapN(ga - 2);
        const int nb = wrapN(gb - 2);
        const int nc = wrapN(gc - 2);
        const int nidx = (na * NG + nb) * NG + nc;
        const float dx = px - xg[nidx];
        const float dy = py - yg[nidx];
        const float dz = pz - zg[nidx];
        const float d2 = fmaf(dz, dz, fmaf(dy, dy, dx * dx));
        if (d2 < two_d2) {
            const float dvx = pvx - vxg[nidx];
            const float dvy = pvy - vyg[nidx];
            const float dvz = pvz - vzg[nidx];
            frx = -(fabsf(fabsf(MU * fyc) + fabsf(MU * fzc) - MU * fxd)
                    * dvx / fmaxf(EPSF, fabsf(dvx)));
            fry = -(fabsf(fabsf(MU * fxc) + fabsf(MU * fzc) - MU * fyd)
                    * dvy / fmaxf(EPSF, fabsf(dvy)));
            // NB: reference uses diffvy in the z-friction numerator (kept).
            frz = -(fabsf(fabsf(MU * fxc) + fabsf(MU * fyc) - MU * fzd)
                    * dvy / fmaxf(EPSF, fabsf(dvz)));
        }
    }
    float* o = out + gidx;
    o[0 * NTOT] = fxc;
    o[1 * NTOT] = fyc;
    o[2 * NTOT] = fzc;
    o[3 * NTOT] = fxd;
    o[4 * NTOT] = fyd;
    o[5 * NTOT] = fzd;
    o[6 * NTOT] = frx;
    o[7 * NTOT] = fry;
    o[8 * NTOT] = frz;
}

// ---------------- Pass 0: reset hit counter (graph-replay determinism) ------
__global__ void reset_kernel() {
    g_count = 0;
}

// ---------------- Pass A: forward-only filter + zero-store + list append ----
__global__ __launch_bounds__(BX * BY * BZ, 4)
void filter_kernel(const float* __restrict__ xg, const float* __restrict__ yg,
                   const float* __restrict__ zg,
                   const float* __restrict__ dptr, float* __restrict__ out)
{
    __shared__ unsigned qpk[TILE];   // bytes: (floor x, floor y, floor z, 0)

    const int lx = threadIdx.x, ly = threadIdx.y, lz = threadIdx.z;
    const int bx0 = blockIdx.x * BX;
    const int by0 = blockIdx.y * BY;
    const int bz0 = blockIdx.z * BZ;
    const int tid = (lz * BY + ly) * BX + lx;

    // halo key build: x,y wrap +-2; z only 0..+2 above (forward offsets)
    for (int idx = tid; idx < TILE; idx += BX * BY * BZ) {
        int tx = idx % TX;
        int r  = idx / TX;
        int ty = r % TY;
        int tz = r / TY;
        int gx = wrapN(bx0 + tx - 2);
        int gy = wrapN(by0 + ty - 2);
        int gz = wrapN(bz0 + tz);
        int g = (gz * NG + gy) * NG + gx;
        qpk[idx] = (unsigned)(int)xg[g] | ((unsigned)(int)yg[g] << 8)
                 | ((unsigned)(int)zg[g] << 16);
    }
    __syncthreads();

    const float d     = *dptr;
    const float two_d = 2.0f * d;
    // byte-filter validity: |dx| < two_d <= 1 => |floor diff| <= 1 per axis
    const bool filter_ok = (two_d <= 1.0f);

    const int cz = lz, cy = ly + 2, cx = lx + 2;   // own z at tile tz = lz
    const int cidx = (cz * TY + cy) * TX + cx;
    const unsigned pq = qpk[cidx];

    const int gz = bz0 + lz, gy = by0 + ly, gx = bx0 + lx;
    const int gidx = (gz * NG + gy) * NG + gx;

    // ---- byte prefilter over the 62 lexicographically-forward offsets ----
    bool need = !filter_ok;
    if (filter_ok) {
        unsigned m0 = ~0u, m1 = ~0u, m2 = ~0u, m3 = ~0u;
        int k = 0;
        #pragma unroll
        for (int oz = 0; oz <= 2; oz++) {
            #pragma unroll
            for (int oy = -2; oy <= 2; oy++) {
                if (oz == 0 && oy < 0) continue;
                #pragma unroll
                for (int ox = -2; ox <= 2; ox++) {
                    if (oz == 0 && oy == 0 && ox < 1) continue;
                    const unsigned nq = qpk[cidx + (oz * TY + oy) * TX + ox];
                    const unsigned v = __vabsdiffu4(pq, nq) & BMASK;
                    const int lane = (k++) & 3;
                    if (lane == 0)      m0 = min(m0, v);
                    else if (lane == 1) m1 = min(m1, v);
                    else if (lane == 2) m2 = min(m2, v);
                    else                m3 = min(m3, v);
                }
            }
        }
        need = (min(min(m0, m1), min(m2, m3)) == 0u);
    }

    // zero all nine outputs for every voxel; pass B overwrites true hits
    float* o = out + gidx;
    #pragma unroll
    for (int q = 0; q < 9; q++) o[q * NTOT] = 0.f;

    // rare (~0.8% of warps): exact forward check; append BOTH pair endpoints
    if (__any_sync(FULLMASK, need)) {
        if (need) {
            const float two_d2 = two_d * two_d;
            const float px = xg[gidx], py = yg[gidx], pz = zg[gidx];
            #pragma unroll 1
            for (int oz = 0; oz <= 2; oz++) {
                #pragma unroll 1
                for (int oy = -2; oy <= 2; oy++) {
                    if (oz == 0 && oy < 0) continue;
                    #pragma unroll 1
                    for (int ox = -2; ox <= 2; ox++) {
                        if (oz == 0 && oy == 0 && ox < 1) continue;
                        const int nidx = (wrapN(gz + oz) * NG + wrapN(gy + oy)) * NG
                                       + wrapN(gx + ox);
                        const float dx = px - xg[nidx];
                        const float dy = py - yg[nidx];
                        const float dz = pz - zg[nidx];
                        const float d2 = fmaf(dz, dz, fmaf(dy, dy, dx * dx));
                        // include d2 == 0: friction needs zero-distance overlaps
                        if (d2 < two_d2) {
                            int i0 = atomicAdd(&g_count, 2);
                            if (i0 + 1 < LCAP) {
                                g_list[i0]     = gidx;
                                g_list[i0 + 1] = nidx;
                            }
                        }
                    }
                }
            }
        }
    }
}

// ---------------- Pass B: evaluate listed voxels exactly --------------------
#define FBLK 256
#define FGRD 64
__global__ __launch_bounds__(FBLK)
void fixup_kernel(const float* __restrict__ xg, const float* __restrict__ yg,
                  const float* __restrict__ zg, const float* __restrict__ vxg,
                  const float* __restrict__ vyg, const float* __restrict__ vzg,
                  const float* __restrict__ dptr, float* __restrict__ out,
                  float eta)
{
    const int n = min(g_count, LCAP);
    const float two_d = 2.0f * (*dptr);
    const int stride = FBLK * FGRD;
    for (int i = blockIdx.x * FBLK + threadIdx.x; i < n; i += stride) {
        const int v = g_list[i];
        const int gx = v % NG;
        const int r  = v / NG;
        const int gy = r % NG;
        const int gz = r / NG;
        // duplicates possible; evaluation is idempotent (identical values)
        exact_voxel_store(gz, gy, gx, two_d, eta,
                          xg, yg, zg, vxg, vyg, vzg, out);
    }
}

extern "C" void kernel_launch(void* const* d_in, const int* in_sizes, int n_in,
                              void* d_out, int out_size)
{
    const float* xg   = (const float*)d_in[0];
    const float* yg   = (const float*)d_in[1];
    const float* zg   = (const float*)d_in[2];
    const float* vxg  = (const float*)d_in[3];
    const float* vyg  = (const float*)d_in[4];
    const float* vzg  = (const float*)d_in[5];
    const float* dptr = (const float*)d_in[6];
    float* out = (float*)d_out;

    // ETA = 2*gamma*sqrt(KN), gamma = alpha/sqrt(alpha^2+1), alpha = -ln(0.7)/pi
    const double alpha = -log(0.7) / M_PI;
    const double gam   = alpha / sqrt(alpha * alpha + 1.0);
    const float  eta   = (float)(2.0 * gam * sqrt(500000.0));

    reset_kernel<<<1, 1>>>();

    dim3 blockA(BX, BY, BZ);
    dim3 gridA(NG / BX, NG / BY, NG / BZ);
    filter_kernel<<<gridA, blockA>>>(xg, yg, zg, dptr, out);

    fixup_kernel<<<FGRD, FBLK>>>(xg, yg, zg, vxg, vyg, vzg, dptr, out, eta);
}